// round 1
// baseline (speedup 1.0000x reference)
#include <cuda_runtime.h>

// Problem constants (fixed by the reference: B=16, N=1024, D=256)
#define BATCH 16
#define NPTS  1024
#define DIM   256

// Scratch: Y[row][0:256] = X@Wu row, Y[row][256:512] = X@Wl row.
// 16384 * 512 * 4B = 32 MB static device array (allocation-free rule).
__device__ float g_Y[16384 * 512];

// ---------------------------------------------------------------------------
// Stage 1: Y = X @ [Wu | Wl]   (M=16384, N=512, K=256)
// 128x128 output tile per block, 256 threads, 8x8 micro-tile per thread.
// ---------------------------------------------------------------------------
__global__ __launch_bounds__(256)
void stage1_xw(const float* __restrict__ X,
               const float* __restrict__ Wu,
               const float* __restrict__ Wl) {
    __shared__ float As[16][128];   // [k][m]  (X tile, transposed)
    __shared__ float Bs[16][128];   // [k][n]  (W tile)

    const int m0 = blockIdx.x * 128;          // 0..16256
    const int n0 = blockIdx.y * 128;          // 0,128,256,384
    const float* Wbase = (n0 < 256) ? Wu : Wl;
    const int    ncol0 = (n0 < 256) ? n0 : (n0 - 256);

    const int tid = threadIdx.x;
    const int tx  = tid & 15;
    const int ty  = tid >> 4;

    float acc[8][8] = {};

    for (int k0 = 0; k0 < DIM; k0 += 16) {
        // A tile: X[m0+r][k0 + c], 128x16 floats = 512 float4, 2 per thread
        #pragma unroll
        for (int i = 0; i < 2; i++) {
            int idx = tid + i * 256;          // 0..511
            int r   = idx >> 2;               // 0..127
            int c4  = idx & 3;                // 0..3
            float4 v = *(const float4*)(X + (size_t)(m0 + r) * DIM + k0 + c4 * 4);
            As[c4 * 4 + 0][r] = v.x;
            As[c4 * 4 + 1][r] = v.y;
            As[c4 * 4 + 2][r] = v.z;
            As[c4 * 4 + 3][r] = v.w;
        }
        // B tile: Wbase[(k0+k)*256 + ncol0 + n], 16x128 floats
        #pragma unroll
        for (int i = 0; i < 2; i++) {
            int idx = tid + i * 256;
            int k   = idx >> 5;               // 0..15
            int n4  = idx & 31;               // 0..31
            float4 v = *(const float4*)(Wbase + (size_t)(k0 + k) * DIM + ncol0 + n4 * 4);
            *(float4*)(&Bs[k][n4 * 4]) = v;
        }
        __syncthreads();

        #pragma unroll
        for (int k = 0; k < 16; k++) {
            float a[8], b[8];
            *(float4*)(a)     = *(const float4*)(&As[k][ty * 8]);
            *(float4*)(a + 4) = *(const float4*)(&As[k][ty * 8 + 4]);
            *(float4*)(b)     = *(const float4*)(&Bs[k][tx * 8]);
            *(float4*)(b + 4) = *(const float4*)(&Bs[k][tx * 8 + 4]);
            #pragma unroll
            for (int i = 0; i < 8; i++)
                #pragma unroll
                for (int j = 0; j < 8; j++)
                    acc[i][j] += a[i] * b[j];
        }
        __syncthreads();
    }

    // Store to scratch Y [16384, 512]
    #pragma unroll
    for (int i = 0; i < 8; i++) {
        float* dst = g_Y + (size_t)(m0 + ty * 8 + i) * 512 + n0 + tx * 8;
        *(float4*)(dst)     = make_float4(acc[i][0], acc[i][1], acc[i][2], acc[i][3]);
        *(float4*)(dst + 4) = make_float4(acc[i][4], acc[i][5], acc[i][6], acc[i][7]);
    }
}

// ---------------------------------------------------------------------------
// Stage 2: adj[b,p,q] = dot(Ysel[b,p,:], X[b,q,:]) + bias_sel
// Per batch: 1024x1024 output, 128x128 tiles, K=256.
// Off-diagonal tiles: single pass (upper or lower). Diagonal tiles: two
// passes (upper then lower) with per-element predicated stores.
// ---------------------------------------------------------------------------
__global__ __launch_bounds__(256)
void stage2_adj(const float* __restrict__ X,
                const float* __restrict__ bu,
                const float* __restrict__ bl,
                float* __restrict__ out) {
    const int qt = blockIdx.x;     // 0..7
    const int pt = blockIdx.y;     // 0..7
    const int b  = blockIdx.z;     // 0..15
    const int p0 = pt * 128, q0 = qt * 128;

    __shared__ float As[16][128];  // [e][p]  (Y tile)
    __shared__ float Bs[16][128];  // [e][q]  (X tile)

    const int tid = threadIdx.x;
    const int tx  = tid & 15;
    const int ty  = tid >> 4;

    const float* Xb = X   + (size_t)b * NPTS * DIM;
    const float* Yb = g_Y + (size_t)b * NPTS * 512;

    const bool do_upper = (pt <= qt);
    const bool do_lower = (pt >= qt);
    const float bias_u = bu[0];
    const float bias_l = bl[0];

    #pragma unroll 1
    for (int pass = 0; pass < 2; pass++) {
        if (pass == 0 && !do_upper) continue;
        if (pass == 1 && !do_lower) continue;
        const int aoff = (pass == 0) ? 0 : 256;

        float acc[8][8] = {};

        for (int k0 = 0; k0 < DIM; k0 += 16) {
            // A tile: Yb[(p0+r)*512 + aoff + k0 + c]
            #pragma unroll
            for (int i = 0; i < 2; i++) {
                int idx = tid + i * 256;
                int r = idx >> 2, c4 = idx & 3;
                float4 v = *(const float4*)(Yb + (size_t)(p0 + r) * 512 + aoff + k0 + c4 * 4);
                As[c4 * 4 + 0][r] = v.x;
                As[c4 * 4 + 1][r] = v.y;
                As[c4 * 4 + 2][r] = v.z;
                As[c4 * 4 + 3][r] = v.w;
            }
            // B tile: Xb[(q0+r)*256 + k0 + c]
            #pragma unroll
            for (int i = 0; i < 2; i++) {
                int idx = tid + i * 256;
                int r = idx >> 2, c4 = idx & 3;
                float4 v = *(const float4*)(Xb + (size_t)(q0 + r) * DIM + k0 + c4 * 4);
                Bs[c4 * 4 + 0][r] = v.x;
                Bs[c4 * 4 + 1][r] = v.y;
                Bs[c4 * 4 + 2][r] = v.z;
                Bs[c4 * 4 + 3][r] = v.w;
            }
            __syncthreads();

            #pragma unroll
            for (int k = 0; k < 16; k++) {
                float a[8], bq[8];
                *(float4*)(a)      = *(const float4*)(&As[k][ty * 8]);
                *(float4*)(a + 4)  = *(const float4*)(&As[k][ty * 8 + 4]);
                *(float4*)(bq)     = *(const float4*)(&Bs[k][tx * 8]);
                *(float4*)(bq + 4) = *(const float4*)(&Bs[k][tx * 8 + 4]);
                #pragma unroll
                for (int i = 0; i < 8; i++)
                    #pragma unroll
                    for (int j = 0; j < 8; j++)
                        acc[i][j] += a[i] * bq[j];
            }
            __syncthreads();
        }

        const float bias = (pass == 0) ? bias_u : bias_l;
        const bool full  = (pass == 0) ? (pt < qt) : (pt > qt);

        #pragma unroll
        for (int i = 0; i < 8; i++) {
            const int p = p0 + ty * 8 + i;
            float* dst = out + (size_t)b * NPTS * NPTS + (size_t)p * NPTS + q0 + tx * 8;
            if (full) {
                *(float4*)(dst)     = make_float4(acc[i][0] + bias, acc[i][1] + bias,
                                                  acc[i][2] + bias, acc[i][3] + bias);
                *(float4*)(dst + 4) = make_float4(acc[i][4] + bias, acc[i][5] + bias,
                                                  acc[i][6] + bias, acc[i][7] + bias);
            } else {
                // diagonal tile: per-element triangle predication
                #pragma unroll
                for (int j = 0; j < 8; j++) {
                    const int q = q0 + tx * 8 + j;
                    const bool sel = (pass == 0) ? (p <= q) : (p > q);
                    if (sel) dst[j] = acc[i][j] + bias;
                }
            }
        }
    }
}

// ---------------------------------------------------------------------------
// kernel_launch
// Inputs (metadata order): feats[16384*256] f32, W_upper[1*256*256] f32,
// b_upper[1] f32, W_lower[1*256*256] f32, b_lower[1] f32, length[16] i32.
// Output: adj [16*1024*1024] f32.
// ---------------------------------------------------------------------------
extern "C" void kernel_launch(void* const* d_in, const int* in_sizes, int n_in,
                              void* d_out, int out_size) {
    const float* feats = (const float*)d_in[0];
    const float* Wu    = (const float*)d_in[1];
    const float* bu    = (const float*)d_in[2];
    const float* Wl    = (const float*)d_in[3];
    const float* bl    = (const float*)d_in[4];
    // d_in[5] = length (always 1024, unused)
    float* out = (float*)d_out;

    dim3 g1(16384 / 128, 512 / 128);   // (128, 4)
    stage1_xw<<<g1, 256>>>(feats, Wu, Wl);

    dim3 g2(NPTS / 128, NPTS / 128, BATCH);  // (8, 8, 16)
    stage2_adj<<<g2, 256>>>(feats, bu, bl, out);
}

// round 3
// speedup vs baseline: 2.1817x; 2.1817x over previous
#include <cuda_runtime.h>
#include <cuda_bf16.h>
#include <cstdint>

#define NPTS 1024
#define DIM  256

// ---------------------------------------------------------------------------
// Scratch (__device__ globals; allocation-free rule). ~48.5 MB.
// ---------------------------------------------------------------------------
__device__ __align__(16) __nv_bfloat16 g_Xhi[16384 * 256];
__device__ __align__(16) __nv_bfloat16 g_Xlo[16384 * 256];
__device__ __align__(16) __nv_bfloat16 g_Wthi[2 * 256 * 256];   // [w][n][k] = W[w][k][n]
__device__ __align__(16) __nv_bfloat16 g_Wtlo[2 * 256 * 256];
__device__ __align__(16) __nv_bfloat16 g_Yhi[16384 * 512];      // cols 0-255 upper, 256-511 lower
__device__ __align__(16) __nv_bfloat16 g_Ylo[16384 * 512];

__device__ __forceinline__ uint32_t smem_u32(const void* p) {
    uint32_t a;
    asm("{ .reg .u64 t; cvta.to.shared.u64 t, %1; cvt.u32.u64 %0, t; }" : "=r"(a) : "l"(p));
    return a;
}
__device__ __forceinline__ uint32_t bfu(__nv_bfloat16 v) {
    return (uint32_t)__bfloat16_as_ushort(v);
}

// HMMA: D += A(16x16 bf16, row) * B(16x8 bf16, col), fp32 acc.
__device__ __forceinline__ void mma16816(float* d, const uint32_t* a, const uint32_t* b) {
    asm volatile(
        "mma.sync.aligned.m16n8k16.row.col.f32.bf16.bf16.f32 "
        "{%0,%1,%2,%3}, {%4,%5,%6,%7}, {%8,%9}, {%0,%1,%2,%3};\n"
        : "+f"(d[0]), "+f"(d[1]), "+f"(d[2]), "+f"(d[3])
        : "r"(a[0]), "r"(a[1]), "r"(a[2]), "r"(a[3]), "r"(b[0]), "r"(b[1]));
}
#define CP_ASYNC16(dst, src) \
    asm volatile("cp.async.cg.shared.global [%0], [%1], 16;" :: "r"(dst), "l"(src))
#define CP_COMMIT() asm volatile("cp.async.commit_group;" ::: "memory")
#define CP_WAIT1()  asm volatile("cp.async.wait_group 1;" ::: "memory")

// SMEM tile geometry: 128 rows x 32 used bf16, padded to 40 bf16 (80B) rows.
// stride 20 words -> (20*g + (l&3) + 8*ks) mod 32 is a perfect bank cover.
#define ROWB 40
#define TILE_BYTES (128 * ROWB * 2)   // 10240
#define BUF_BYTES  (4 * TILE_BYTES)   // 40960 (Ah, Al, Bh, Bl)
#define SMEM_TOTAL (2 * BUF_BYTES)    // 81920

// Fill one buffer: 4 tiles x 128 rows x 64B (= 4 x 16B) via cp.async.
__device__ __forceinline__ void fill_buf(uint32_t sbase,
                                         const __nv_bfloat16* ah, const __nv_bfloat16* al,
                                         const __nv_bfloat16* bh, const __nv_bfloat16* bl,
                                         int strideA, int strideB, int k0, int tid) {
    #pragma unroll
    for (int i = 0; i < 8; i++) {
        int u = tid + i * 256;
        int tile = u >> 9, rem = u & 511, r = rem >> 2, c = rem & 3;
        const __nv_bfloat16* src = (tile == 0) ? ah : (tile == 1) ? al : (tile == 2) ? bh : bl;
        int stride = (tile < 2) ? strideA : strideB;
        const __nv_bfloat16* g = src + (size_t)r * stride + k0 + c * 8;
        uint32_t dst = sbase + tile * TILE_BYTES + r * (ROWB * 2) + c * 16;
        CP_ASYNC16(dst, g);
    }
}

// Fragment loads (conflict-free LDS.32).
__device__ __forceinline__ void lda(uint32_t* f, const __nv_bfloat16* t, int row, int kc) {
    f[0] = *(const uint32_t*)(t + (size_t)(row)     * ROWB + kc);
    f[1] = *(const uint32_t*)(t + (size_t)(row + 8) * ROWB + kc);
    f[2] = *(const uint32_t*)(t + (size_t)(row)     * ROWB + kc + 8);
    f[3] = *(const uint32_t*)(t + (size_t)(row + 8) * ROWB + kc + 8);
}
__device__ __forceinline__ void ldb(uint32_t* f, const __nv_bfloat16* t, int row, int kc) {
    f[0] = *(const uint32_t*)(t + (size_t)row * ROWB + kc);
    f[1] = *(const uint32_t*)(t + (size_t)row * ROWB + kc + 8);
}

// One K-chunk of the split-bf16 GEMM: acc += Ah*Bh + Ah*Bl + Al*Bh.
// Warp computes 64x32: 4 m-tiles x 4 n-tiles.
__device__ __forceinline__ void compute_chunk(float acc[4][4][4], const char* buf,
                                              int warp_m, int warp_n, int lane) {
    const __nv_bfloat16* Ah = (const __nv_bfloat16*)(buf);
    const __nv_bfloat16* Al = (const __nv_bfloat16*)(buf + TILE_BYTES);
    const __nv_bfloat16* Bh = (const __nv_bfloat16*)(buf + 2 * TILE_BYTES);
    const __nv_bfloat16* Bl = (const __nv_bfloat16*)(buf + 3 * TILE_BYTES);
    const int g = lane >> 2;
    const int kc0 = (lane & 3) * 2;
    #pragma unroll
    for (int ks = 0; ks < 2; ks++) {
        const int kc = kc0 + ks * 16;
        uint32_t aH[4][4], bH[4][2];
        #pragma unroll
        for (int mt = 0; mt < 4; mt++) lda(aH[mt], Ah, warp_m * 64 + mt * 16 + g, kc);
        #pragma unroll
        for (int nt = 0; nt < 4; nt++) ldb(bH[nt], Bh, warp_n * 32 + nt * 8 + g, kc);
        #pragma unroll
        for (int mt = 0; mt < 4; mt++)
            #pragma unroll
            for (int nt = 0; nt < 4; nt++) mma16816(acc[mt][nt], aH[mt], bH[nt]);
        uint32_t bL[4][2];
        #pragma unroll
        for (int nt = 0; nt < 4; nt++) ldb(bL[nt], Bl, warp_n * 32 + nt * 8 + g, kc);
        #pragma unroll
        for (int mt = 0; mt < 4; mt++)
            #pragma unroll
            for (int nt = 0; nt < 4; nt++) mma16816(acc[mt][nt], aH[mt], bL[nt]);
        uint32_t aL[4][4];
        #pragma unroll
        for (int mt = 0; mt < 4; mt++) lda(aL[mt], Al, warp_m * 64 + mt * 16 + g, kc);
        #pragma unroll
        for (int mt = 0; mt < 4; mt++)
            #pragma unroll
            for (int nt = 0; nt < 4; nt++) mma16816(acc[mt][nt], aL[mt], bH[nt]);
    }
}

// Full pipelined 128x128x256 tile into acc.
__device__ __forceinline__ void gemm_tile(float acc[4][4][4], char* smem,
                                          const __nv_bfloat16* ah, const __nv_bfloat16* al,
                                          const __nv_bfloat16* bh, const __nv_bfloat16* bl,
                                          int strideA, int strideB,
                                          int warp_m, int warp_n, int lane, int tid) {
    const uint32_t sbase = smem_u32(smem);
    fill_buf(sbase, ah, al, bh, bl, strideA, strideB, 0, tid);
    CP_COMMIT();
    #pragma unroll 1
    for (int c = 0; c < 8; c++) {
        if (c < 7) fill_buf(sbase + ((c + 1) & 1) * BUF_BYTES, ah, al, bh, bl,
                            strideA, strideB, (c + 1) * 32, tid);
        CP_COMMIT();
        CP_WAIT1();
        __syncthreads();
        compute_chunk(acc, smem + (c & 1) * BUF_BYTES, warp_m, warp_n, lane);
        __syncthreads();
    }
}

// ---------------------------------------------------------------------------
// Prep: split X and W^T into bf16 hi/lo planes.
// ---------------------------------------------------------------------------
__global__ __launch_bounds__(256) void prep_split_x(const float* __restrict__ X) {
    int idx = blockIdx.x * 256 + threadIdx.x;          // 1M float4 groups
    float4 v = reinterpret_cast<const float4*>(X)[idx];
    __nv_bfloat16 h0 = __float2bfloat16(v.x), h1 = __float2bfloat16(v.y);
    __nv_bfloat16 h2 = __float2bfloat16(v.z), h3 = __float2bfloat16(v.w);
    __nv_bfloat16 l0 = __float2bfloat16(v.x - __bfloat162float(h0));
    __nv_bfloat16 l1 = __float2bfloat16(v.y - __bfloat162float(h1));
    __nv_bfloat16 l2 = __float2bfloat16(v.z - __bfloat162float(h2));
    __nv_bfloat16 l3 = __float2bfloat16(v.w - __bfloat162float(h3));
    reinterpret_cast<uint2*>(g_Xhi)[idx] =
        make_uint2(bfu(h0) | (bfu(h1) << 16), bfu(h2) | (bfu(h3) << 16));
    reinterpret_cast<uint2*>(g_Xlo)[idx] =
        make_uint2(bfu(l0) | (bfu(l1) << 16), bfu(l2) | (bfu(l3) << 16));
}

__global__ __launch_bounds__(256) void prep_split_w(const float* __restrict__ Wu,
                                                    const float* __restrict__ Wl) {
    int idx = blockIdx.x * 256 + threadIdx.x;          // 131072 elements
    int w = idx >> 16, rem = idx & 65535;
    int n = rem >> 8, k = rem & 255;
    float v = (w ? Wl : Wu)[k * 256 + n];
    __nv_bfloat16 h = __float2bfloat16(v);
    __nv_bfloat16 l = __float2bfloat16(v - __bfloat162float(h));
    g_Wthi[idx] = h;
    g_Wtlo[idx] = l;
}

// ---------------------------------------------------------------------------
// Stage 1: Y = X @ [Wu | Wl].  grid (128, 4): m0 = bx*128; by -> 128-col slab.
// Epilogue stores Y pre-split into bf16 hi/lo planes.
// ---------------------------------------------------------------------------
__global__ __launch_bounds__(256) void stage1_xw() {
    extern __shared__ char smem[];
    const int tid = threadIdx.x, lane = tid & 31, wid = tid >> 5;
    const int warp_m = wid >> 2, warp_n = wid & 3;
    const int m0 = blockIdx.x * 128;
    const int ny = blockIdx.y;                 // 0..3
    const int w = ny >> 1;

    const __nv_bfloat16* ah = g_Xhi + (size_t)m0 * 256;
    const __nv_bfloat16* al = g_Xlo + (size_t)m0 * 256;
    const __nv_bfloat16* bh = g_Wthi + (size_t)w * 65536 + (size_t)(ny & 1) * 128 * 256;
    const __nv_bfloat16* bl = g_Wtlo + (size_t)w * 65536 + (size_t)(ny & 1) * 128 * 256;

    float acc[4][4][4] = {};
    gemm_tile(acc, smem, ah, al, bh, bl, 256, 256, warp_m, warp_n, lane, tid);

    // Epilogue: split each fp32 into bf16 hi/lo and store to g_Yhi / g_Ylo.
    const int g = lane >> 2, c2 = (lane & 3) * 2;
    #pragma unroll
    for (int mt = 0; mt < 4; mt++) {
        #pragma unroll
        for (int nt = 0; nt < 4; nt++) {
            const int m = m0 + warp_m * 64 + mt * 16 + g;
            const int n = ny * 128 + warp_n * 32 + nt * 8 + c2;
            #pragma unroll
            for (int h = 0; h < 2; h++) {      // h=0: rows g, h=1: rows g+8
                float x = acc[mt][nt][2 * h];
                float y = acc[mt][nt][2 * h + 1];
                __nv_bfloat16 xh = __float2bfloat16(x), yh = __float2bfloat16(y);
                __nv_bfloat16 xl = __float2bfloat16(x - __bfloat162float(xh));
                __nv_bfloat16 yl = __float2bfloat16(y - __bfloat162float(yh));
                size_t off = (size_t)(m + 8 * h) * 512 + n;
                *(uint32_t*)(g_Yhi + off) = bfu(xh) | (bfu(yh) << 16);
                *(uint32_t*)(g_Ylo + off) = bfu(xl) | (bfu(yl) << 16);
            }
        }
    }
}

// ---------------------------------------------------------------------------
// Stage 2: adj[b,p,q] = dot(Ysel[b,p,:], X[b,q,:]) + bias_sel.
// grid (8, 8, 16). Off-diag tiles one pass; diagonal tiles two passes with
// per-element triangle predication.
// ---------------------------------------------------------------------------
__global__ __launch_bounds__(256) void stage2_adj(const float* __restrict__ bu,
                                                  const float* __restrict__ bl,
                                                  float* __restrict__ out) {
    extern __shared__ char smem[];
    const int tid = threadIdx.x, lane = tid & 31, wid = tid >> 5;
    const int warp_m = wid >> 2, warp_n = wid & 3;
    const int qt = blockIdx.x, pt = blockIdx.y, b = blockIdx.z;
    const int p0 = pt * 128, q0 = qt * 128;

    const float biasU = __ldg(bu), biasL = __ldg(bl);
    const __nv_bfloat16* xh = g_Xhi + (size_t)(b * NPTS + q0) * 256;
    const __nv_bfloat16* xl = g_Xlo + (size_t)(b * NPTS + q0) * 256;

    #pragma unroll 1
    for (int pass = 0; pass < 2; pass++) {
        if (pass == 0 && pt > qt) continue;
        if (pass == 1 && pt < qt) continue;

        const __nv_bfloat16* yh = g_Yhi + (size_t)(b * NPTS + p0) * 512 + pass * 256;
        const __nv_bfloat16* yl = g_Ylo + (size_t)(b * NPTS + p0) * 512 + pass * 256;

        float acc[4][4][4] = {};
        gemm_tile(acc, smem, yh, yl, xh, xl, 512, 256, warp_m, warp_n, lane, tid);

        const float bias = pass ? biasL : biasU;
        const int g = lane >> 2, c2 = (lane & 3) * 2;
        #pragma unroll
        for (int mt = 0; mt < 4; mt++) {
            #pragma unroll
            for (int nt = 0; nt < 4; nt++) {
                const int q = q0 + warp_n * 32 + nt * 8 + c2;
                #pragma unroll
                for (int h = 0; h < 2; h++) {
                    const int p = p0 + warp_m * 64 + mt * 16 + g + 8 * h;
                    float* dst = out + ((size_t)b << 20) + ((size_t)p << 10) + q;
                    float v0 = acc[mt][nt][2 * h] + bias;
                    float v1 = acc[mt][nt][2 * h + 1] + bias;
                    if (pt != qt) {
                        *(float2*)dst = make_float2(v0, v1);
                    } else if (pass == 0) {
                        if (p <= q)     dst[0] = v0;
                        if (p <= q + 1) dst[1] = v1;
                    } else {
                        if (p > q)      dst[0] = v0;
                        if (p > q + 1)  dst[1] = v1;
                    }
                }
            }
        }
        __syncthreads();
    }
}

// ---------------------------------------------------------------------------
// kernel_launch
// Inputs: feats[16384*256] f32, W_upper[256*256] f32, b_upper[1] f32,
//         W_lower[256*256] f32, b_lower[1] f32, length[16] i32 (unused).
// Output: adj [16*1024*1024] f32.
// ---------------------------------------------------------------------------
extern "C" void kernel_launch(void* const* d_in, const int* in_sizes, int n_in,
                              void* d_out, int out_size) {
    const float* feats = (const float*)d_in[0];
    const float* Wu    = (const float*)d_in[1];
    const float* bu    = (const float*)d_in[2];
    const float* Wl    = (const float*)d_in[3];
    const float* bl    = (const float*)d_in[4];
    float* out = (float*)d_out;

    cudaFuncSetAttribute(stage1_xw,  cudaFuncAttributeMaxDynamicSharedMemorySize, SMEM_TOTAL);
    cudaFuncSetAttribute(stage2_adj, cudaFuncAttributeMaxDynamicSharedMemorySize, SMEM_TOTAL);

    prep_split_x<<<4096, 256>>>(feats);
    prep_split_w<<<512, 256>>>(Wu, Wl);
    stage1_xw<<<dim3(128, 4), 256, SMEM_TOTAL>>>();
    stage2_adj<<<dim3(8, 8, 16), 256, SMEM_TOTAL>>>(bu, bl, out);
}

// round 4
// speedup vs baseline: 2.2446x; 1.0288x over previous
#include <cuda_runtime.h>
#include <cuda_bf16.h>
#include <cstdint>

#define NPTS 1024
#define DIM  256

// ---------------------------------------------------------------------------
// Scratch (__device__ globals; allocation-free rule). ~48.5 MB.
// ---------------------------------------------------------------------------
__device__ __align__(16) __nv_bfloat16 g_Xhi[16384 * 256];
__device__ __align__(16) __nv_bfloat16 g_Xlo[16384 * 256];
__device__ __align__(16) __nv_bfloat16 g_Wthi[2 * 256 * 256];   // [w][n][k] = W[w][k][n]
__device__ __align__(16) __nv_bfloat16 g_Wtlo[2 * 256 * 256];
__device__ __align__(16) __nv_bfloat16 g_Yhi[16384 * 512];      // cols 0-255 upper, 256-511 lower
__device__ __align__(16) __nv_bfloat16 g_Ylo[16384 * 512];

__device__ __forceinline__ uint32_t smem_u32(const void* p) {
    uint32_t a;
    asm("{ .reg .u64 t; cvta.to.shared.u64 t, %1; cvt.u32.u64 %0, t; }" : "=r"(a) : "l"(p));
    return a;
}
__device__ __forceinline__ uint32_t bfu(__nv_bfloat16 v) {
    return (uint32_t)__bfloat16_as_ushort(v);
}

// HMMA: D += A(16x16 bf16, row) * B(16x8 bf16, col), fp32 acc.
__device__ __forceinline__ void mma16816(float* d, const uint32_t* a, const uint32_t* b) {
    asm volatile(
        "mma.sync.aligned.m16n8k16.row.col.f32.bf16.bf16.f32 "
        "{%0,%1,%2,%3}, {%4,%5,%6,%7}, {%8,%9}, {%0,%1,%2,%3};\n"
        : "+f"(d[0]), "+f"(d[1]), "+f"(d[2]), "+f"(d[3])
        : "r"(a[0]), "r"(a[1]), "r"(a[2]), "r"(a[3]), "r"(b[0]), "r"(b[1]));
}
#define CP_ASYNC16(dst, src) \
    asm volatile("cp.async.cg.shared.global [%0], [%1], 16;" :: "r"(dst), "l"(src))
#define CP_COMMIT() asm volatile("cp.async.commit_group;" ::: "memory")
#define CP_WAIT1()  asm volatile("cp.async.wait_group 1;" ::: "memory")

// SMEM tile geometry: 128 rows x 32 used bf16, padded to 40 bf16 (80B) rows.
// stride 20 words -> fragment LDS.32 are bank-conflict-free.
#define ROWB 40
#define TILE_BYTES (128 * ROWB * 2)   // 10240
#define BUF_BYTES  (4 * TILE_BYTES)   // 40960 (Ah, Al, Bh, Bl)
#define SMEM_TOTAL (2 * BUF_BYTES)    // 81920  (x2 CTAs = 160K <= 227K/SM)

// Fill one buffer: 4 tiles x 128 rows x 64B (= 4 x 16B) via cp.async.
__device__ __forceinline__ void fill_buf(uint32_t sbase,
                                         const __nv_bfloat16* ah, const __nv_bfloat16* al,
                                         const __nv_bfloat16* bh, const __nv_bfloat16* bl,
                                         int strideA, int strideB, int k0, int tid) {
    #pragma unroll
    for (int i = 0; i < 8; i++) {
        int u = tid + i * 256;
        int tile = u >> 9, rem = u & 511, r = rem >> 2, c = rem & 3;
        const __nv_bfloat16* src = (tile == 0) ? ah : (tile == 1) ? al : (tile == 2) ? bh : bl;
        int stride = (tile < 2) ? strideA : strideB;
        const __nv_bfloat16* g = src + (size_t)r * stride + k0 + c * 8;
        uint32_t dst = sbase + tile * TILE_BYTES + r * (ROWB * 2) + c * 16;
        CP_ASYNC16(dst, g);
    }
}

// Fragment loads (conflict-free LDS.32).
__device__ __forceinline__ void lda(uint32_t* f, const __nv_bfloat16* t, int row, int kc) {
    f[0] = *(const uint32_t*)(t + (size_t)(row)     * ROWB + kc);
    f[1] = *(const uint32_t*)(t + (size_t)(row + 8) * ROWB + kc);
    f[2] = *(const uint32_t*)(t + (size_t)(row)     * ROWB + kc + 8);
    f[3] = *(const uint32_t*)(t + (size_t)(row + 8) * ROWB + kc + 8);
}
__device__ __forceinline__ void ldb(uint32_t* f, const __nv_bfloat16* t, int row, int kc) {
    f[0] = *(const uint32_t*)(t + (size_t)row * ROWB + kc);
    f[1] = *(const uint32_t*)(t + (size_t)row * ROWB + kc + 8);
}

// One K-chunk: acc += Ah*Bh + Ah*Bl + Al*Bh. Warp tile 64x32.
// Ordered to keep peak live registers low (aL loaded only after bL dies).
__device__ __forceinline__ void compute_chunk(float acc[4][4][4], const char* buf,
                                              int warp_m, int warp_n, int lane) {
    const __nv_bfloat16* Ah = (const __nv_bfloat16*)(buf);
    const __nv_bfloat16* Al = (const __nv_bfloat16*)(buf + TILE_BYTES);
    const __nv_bfloat16* Bh = (const __nv_bfloat16*)(buf + 2 * TILE_BYTES);
    const __nv_bfloat16* Bl = (const __nv_bfloat16*)(buf + 3 * TILE_BYTES);
    const int g = lane >> 2;
    const int kc0 = (lane & 3) * 2;
    #pragma unroll
    for (int ks = 0; ks < 2; ks++) {
        const int kc = kc0 + ks * 16;
        uint32_t aH[4][4], bH[4][2];
        #pragma unroll
        for (int mt = 0; mt < 4; mt++) lda(aH[mt], Ah, warp_m * 64 + mt * 16 + g, kc);
        #pragma unroll
        for (int nt = 0; nt < 4; nt++) ldb(bH[nt], Bh, warp_n * 32 + nt * 8 + g, kc);
        #pragma unroll
        for (int mt = 0; mt < 4; mt++)
            #pragma unroll
            for (int nt = 0; nt < 4; nt++) mma16816(acc[mt][nt], aH[mt], bH[nt]);
        {
            uint32_t bL[4][2];
            #pragma unroll
            for (int nt = 0; nt < 4; nt++) ldb(bL[nt], Bl, warp_n * 32 + nt * 8 + g, kc);
            #pragma unroll
            for (int mt = 0; mt < 4; mt++)
                #pragma unroll
                for (int nt = 0; nt < 4; nt++) mma16816(acc[mt][nt], aH[mt], bL[nt]);
        }
        {
            uint32_t aL[4][4];
            #pragma unroll
            for (int mt = 0; mt < 4; mt++) lda(aL[mt], Al, warp_m * 64 + mt * 16 + g, kc);
            #pragma unroll
            for (int mt = 0; mt < 4; mt++)
                #pragma unroll
                for (int nt = 0; nt < 4; nt++) mma16816(acc[mt][nt], aL[mt], bH[nt]);
        }
    }
}

// Full pipelined 128x128x256 tile into acc.
__device__ __forceinline__ void gemm_tile(float acc[4][4][4], char* smem,
                                          const __nv_bfloat16* ah, const __nv_bfloat16* al,
                                          const __nv_bfloat16* bh, const __nv_bfloat16* bl,
                                          int strideA, int strideB,
                                          int warp_m, int warp_n, int lane, int tid) {
    const uint32_t sbase = smem_u32(smem);
    fill_buf(sbase, ah, al, bh, bl, strideA, strideB, 0, tid);
    CP_COMMIT();
    #pragma unroll 1
    for (int c = 0; c < 8; c++) {
        if (c < 7) fill_buf(sbase + ((c + 1) & 1) * BUF_BYTES, ah, al, bh, bl,
                            strideA, strideB, (c + 1) * 32, tid);
        CP_COMMIT();
        CP_WAIT1();
        __syncthreads();
        compute_chunk(acc, smem + (c & 1) * BUF_BYTES, warp_m, warp_n, lane);
        __syncthreads();
    }
}

// ---------------------------------------------------------------------------
// Prep: split X and W^T into bf16 hi/lo planes.
// ---------------------------------------------------------------------------
__global__ __launch_bounds__(256) void prep_split_x(const float* __restrict__ X) {
    int idx = blockIdx.x * 256 + threadIdx.x;          // 1M float4 groups
    float4 v = reinterpret_cast<const float4*>(X)[idx];
    __nv_bfloat16 h0 = __float2bfloat16(v.x), h1 = __float2bfloat16(v.y);
    __nv_bfloat16 h2 = __float2bfloat16(v.z), h3 = __float2bfloat16(v.w);
    __nv_bfloat16 l0 = __float2bfloat16(v.x - __bfloat162float(h0));
    __nv_bfloat16 l1 = __float2bfloat16(v.y - __bfloat162float(h1));
    __nv_bfloat16 l2 = __float2bfloat16(v.z - __bfloat162float(h2));
    __nv_bfloat16 l3 = __float2bfloat16(v.w - __bfloat162float(h3));
    reinterpret_cast<uint2*>(g_Xhi)[idx] =
        make_uint2(bfu(h0) | (bfu(h1) << 16), bfu(h2) | (bfu(h3) << 16));
    reinterpret_cast<uint2*>(g_Xlo)[idx] =
        make_uint2(bfu(l0) | (bfu(l1) << 16), bfu(l2) | (bfu(l3) << 16));
}

__global__ __launch_bounds__(256) void prep_split_w(const float* __restrict__ Wu,
                                                    const float* __restrict__ Wl) {
    int idx = blockIdx.x * 256 + threadIdx.x;          // 131072 elements
    int w = idx >> 16, rem = idx & 65535;
    int n = rem >> 8, k = rem & 255;
    float v = (w ? Wl : Wu)[k * 256 + n];
    __nv_bfloat16 h = __float2bfloat16(v);
    __nv_bfloat16 l = __float2bfloat16(v - __bfloat162float(h));
    g_Wthi[idx] = h;
    g_Wtlo[idx] = l;
}

// ---------------------------------------------------------------------------
// Stage 1: Y = X @ [Wu | Wl].  grid (128, 4): m0 = bx*128; by -> 128-col slab.
// ---------------------------------------------------------------------------
__global__ __launch_bounds__(256, 2) void stage1_xw() {
    extern __shared__ char smem[];
    const int tid = threadIdx.x, lane = tid & 31, wid = tid >> 5;
    const int warp_m = wid >> 2, warp_n = wid & 3;
    const int m0 = blockIdx.x * 128;
    const int ny = blockIdx.y;                 // 0..3
    const int w = ny >> 1;

    const __nv_bfloat16* ah = g_Xhi + (size_t)m0 * 256;
    const __nv_bfloat16* al = g_Xlo + (size_t)m0 * 256;
    const __nv_bfloat16* bh = g_Wthi + (size_t)w * 65536 + (size_t)(ny & 1) * 128 * 256;
    const __nv_bfloat16* bl = g_Wtlo + (size_t)w * 65536 + (size_t)(ny & 1) * 128 * 256;

    float acc[4][4][4] = {};
    gemm_tile(acc, smem, ah, al, bh, bl, 256, 256, warp_m, warp_n, lane, tid);

    // Epilogue: split each fp32 into bf16 hi/lo and store to g_Yhi / g_Ylo.
    const int g = lane >> 2, c2 = (lane & 3) * 2;
    #pragma unroll
    for (int mt = 0; mt < 4; mt++) {
        #pragma unroll
        for (int nt = 0; nt < 4; nt++) {
            const int m = m0 + warp_m * 64 + mt * 16 + g;
            const int n = ny * 128 + warp_n * 32 + nt * 8 + c2;
            #pragma unroll
            for (int h = 0; h < 2; h++) {      // h=0: rows g, h=1: rows g+8
                float x = acc[mt][nt][2 * h];
                float y = acc[mt][nt][2 * h + 1];
                __nv_bfloat16 xh = __float2bfloat16(x), yh = __float2bfloat16(y);
                __nv_bfloat16 xl = __float2bfloat16(x - __bfloat162float(xh));
                __nv_bfloat16 yl = __float2bfloat16(y - __bfloat162float(yh));
                size_t off = (size_t)(m + 8 * h) * 512 + n;
                *(uint32_t*)(g_Yhi + off) = bfu(xh) | (bfu(yh) << 16);
                *(uint32_t*)(g_Ylo + off) = bfu(xl) | (bfu(yl) << 16);
            }
        }
    }
}

// ---------------------------------------------------------------------------
// Stage 2: adj[b,p,q] = dot(Ysel[b,p,:], X[b,q,:]) + bias_sel.
// grid (8, 8, 16). Off-diag tiles one pass; diag tiles two passes.
// ---------------------------------------------------------------------------
__global__ __launch_bounds__(256, 2) void stage2_adj(const float* __restrict__ bu,
                                                     const float* __restrict__ bl,
                                                     float* __restrict__ out) {
    extern __shared__ char smem[];
    const int tid = threadIdx.x, lane = tid & 31, wid = tid >> 5;
    const int warp_m = wid >> 2, warp_n = wid & 3;
    const int qt = blockIdx.x, pt = blockIdx.y, b = blockIdx.z;
    const int p0 = pt * 128, q0 = qt * 128;

    const float biasU = __ldg(bu), biasL = __ldg(bl);
    const __nv_bfloat16* xh = g_Xhi + (size_t)(b * NPTS + q0) * 256;
    const __nv_bfloat16* xl = g_Xlo + (size_t)(b * NPTS + q0) * 256;

    #pragma unroll 1
    for (int pass = 0; pass < 2; pass++) {
        if (pass == 0 && pt > qt) continue;
        if (pass == 1 && pt < qt) continue;

        const __nv_bfloat16* yh = g_Yhi + (size_t)(b * NPTS + p0) * 512 + pass * 256;
        const __nv_bfloat16* yl = g_Ylo + (size_t)(b * NPTS + p0) * 512 + pass * 256;

        float acc[4][4][4] = {};
        gemm_tile(acc, smem, yh, yl, xh, xl, 512, 256, warp_m, warp_n, lane, tid);

        const float bias = pass ? biasL : biasU;
        const int g = lane >> 2, c2 = (lane & 3) * 2;
        #pragma unroll
        for (int mt = 0; mt < 4; mt++) {
            #pragma unroll
            for (int nt = 0; nt < 4; nt++) {
                const int q = q0 + warp_n * 32 + nt * 8 + c2;
                #pragma unroll
                for (int h = 0; h < 2; h++) {
                    const int p = p0 + warp_m * 64 + mt * 16 + g + 8 * h;
                    float* dst = out + ((size_t)b << 20) + ((size_t)p << 10) + q;
                    float v0 = acc[mt][nt][2 * h] + bias;
                    float v1 = acc[mt][nt][2 * h + 1] + bias;
                    if (pt != qt) {
                        *(float2*)dst = make_float2(v0, v1);
                    } else if (pass == 0) {
                        if (p <= q)     dst[0] = v0;
                        if (p <= q + 1) dst[1] = v1;
                    } else {
                        if (p > q)      dst[0] = v0;
                        if (p > q + 1)  dst[1] = v1;
                    }
                }
            }
        }
        __syncthreads();
    }
}

// ---------------------------------------------------------------------------
// kernel_launch
// ---------------------------------------------------------------------------
extern "C" void kernel_launch(void* const* d_in, const int* in_sizes, int n_in,
                              void* d_out, int out_size) {
    const float* feats = (const float*)d_in[0];
    const float* Wu    = (const float*)d_in[1];
    const float* bu    = (const float*)d_in[2];
    const float* Wl    = (const float*)d_in[3];
    const float* bl    = (const float*)d_in[4];
    float* out = (float*)d_out;

    cudaFuncSetAttribute(stage1_xw,  cudaFuncAttributeMaxDynamicSharedMemorySize, SMEM_TOTAL);
    cudaFuncSetAttribute(stage2_adj, cudaFuncAttributeMaxDynamicSharedMemorySize, SMEM_TOTAL);

    prep_split_x<<<4096, 256>>>(feats);
    prep_split_w<<<512, 256>>>(Wu, Wl);
    stage1_xw<<<dim3(128, 4), 256, SMEM_TOTAL>>>();
    stage2_adj<<<dim3(8, 8, 16), 256, SMEM_TOTAL>>>(bu, bl, out);
}

// round 5
// speedup vs baseline: 2.8938x; 1.2892x over previous
#include <cuda_runtime.h>
#include <cuda_bf16.h>
#include <cstdint>

#define NPTS 1024
#define DIM  256

// ---------------------------------------------------------------------------
// Scratch (__device__ globals; allocation-free rule). ~48.5 MB.
// ---------------------------------------------------------------------------
__device__ __align__(16) __nv_bfloat16 g_Xhi[16384 * 256];
__device__ __align__(16) __nv_bfloat16 g_Xlo[16384 * 256];
__device__ __align__(16) __nv_bfloat16 g_Wthi[2 * 256 * 256];   // [w][n][k] = W[w][k][n]
__device__ __align__(16) __nv_bfloat16 g_Wtlo[2 * 256 * 256];
__device__ __align__(16) __nv_bfloat16 g_Yhi[16384 * 512];      // cols 0-255 upper, 256-511 lower
__device__ __align__(16) __nv_bfloat16 g_Ylo[16384 * 512];

__device__ __forceinline__ uint32_t smem_u32(const void* p) {
    uint32_t a;
    asm("{ .reg .u64 t; cvta.to.shared.u64 t, %1; cvt.u32.u64 %0, t; }" : "=r"(a) : "l"(p));
    return a;
}
__device__ __forceinline__ uint32_t bfu(__nv_bfloat16 v) {
    return (uint32_t)__bfloat16_as_ushort(v);
}

// HMMA: D += A(16x16 bf16, row) * B(16x8 bf16, col), fp32 acc.
__device__ __forceinline__ void mma16816(float* d, const uint32_t* a, const uint32_t* b) {
    asm volatile(
        "mma.sync.aligned.m16n8k16.row.col.f32.bf16.bf16.f32 "
        "{%0,%1,%2,%3}, {%4,%5,%6,%7}, {%8,%9}, {%0,%1,%2,%3};\n"
        : "+f"(d[0]), "+f"(d[1]), "+f"(d[2]), "+f"(d[3])
        : "r"(a[0]), "r"(a[1]), "r"(a[2]), "r"(a[3]), "r"(b[0]), "r"(b[1]));
}
#define LDSM4(r0, r1, r2, r3, addr) \
    asm volatile("ldmatrix.sync.aligned.m8n8.x4.shared.b16 {%0,%1,%2,%3}, [%4];" \
        : "=r"(r0), "=r"(r1), "=r"(r2), "=r"(r3) : "r"(addr))
#define CP_ASYNC16(dst, src) \
    asm volatile("cp.async.cg.shared.global [%0], [%1], 16;" :: "r"(dst), "l"(src))
#define CP_COMMIT() asm volatile("cp.async.commit_group;" ::: "memory")
#define CP_WAIT1()  asm volatile("cp.async.wait_group 1;" ::: "memory")
#define CP_WAIT0()  asm volatile("cp.async.wait_group 0;" ::: "memory")

// SMEM: 64B rows, XOR quad swizzle: off(r, q) = r*64 + ((q + (r>>1)) & 3)*16.
// -> every ldmatrix 8-row x 16B phase covers 32 distinct banks (conflict-free)
// -> 16B-aligned cp.async destinations, zero padding.
#define TILE_BYTES 8192               // 128 rows x 64 B
#define BUF_BYTES  (4 * TILE_BYTES)   // Ah, Al, Bh, Bl = 32768
#define STAGES 3
#define SMEM_TOTAL (STAGES * BUF_BYTES)   // 98304; x2 CTAs = 192K <= 228K/SM

__device__ __forceinline__ uint32_t swz(int r, int q) {
    return (uint32_t)(r * 64 + (((q + (r >> 1)) & 3) << 4));
}

// Fill one buffer: 4 tiles x 128 rows x 64B via 2048 cp.async of 16B.
__device__ __forceinline__ void fill_buf(uint32_t sbase,
                                         const __nv_bfloat16* ah, const __nv_bfloat16* al,
                                         const __nv_bfloat16* bh, const __nv_bfloat16* bl,
                                         int strideA, int strideB, int k0, int tid) {
    #pragma unroll
    for (int i = 0; i < 8; i++) {
        int u = tid + i * 256;
        int tile = u >> 9, rem = u & 511, r = rem >> 2, q = rem & 3;
        const __nv_bfloat16* src = (tile == 0) ? ah : (tile == 1) ? al : (tile == 2) ? bh : bl;
        int stride = (tile < 2) ? strideA : strideB;
        const __nv_bfloat16* g = src + (size_t)r * stride + k0 + q * 8;
        uint32_t dst = sbase + tile * TILE_BYTES + swz(r, q);
        CP_ASYNC16(dst, g);
    }
}

// One K-chunk: acc += Ah*Bh + Ah*Bl + Al*Bh. Warp tile 64x32, ldmatrix frags.
__device__ __forceinline__ void compute_chunk(float acc[4][4][4], uint32_t bufu,
                                              int warp_m, int warp_n, int lane) {
    // ldmatrix per-lane row/quad assignment
    const int arow = (lane & 7) + ((lane >> 3) & 1) * 8;   // A quadrants: m0k0,m8k0,m0k8,m8k8
    const int aqad = lane >> 4;
    const int brow = (lane & 7) + ((lane >> 4) & 1) * 8;   // B quadrants: n0k0,n0k8,n8k0,n8k8
    const int bqad = (lane >> 3) & 1;
    const uint32_t AH = bufu, AL = bufu + TILE_BYTES;
    const uint32_t BH = bufu + 2 * TILE_BYTES, BL = bufu + 3 * TILE_BYTES;

    #pragma unroll
    for (int ks = 0; ks < 2; ks++) {
        const int q0 = 2 * ks;
        uint32_t aH[4][4], bH[4][2];
        #pragma unroll
        for (int mt = 0; mt < 4; mt++) {
            int r = warp_m * 64 + mt * 16 + arow;
            LDSM4(aH[mt][0], aH[mt][1], aH[mt][2], aH[mt][3], AH + swz(r, q0 + aqad));
        }
        #pragma unroll
        for (int np = 0; np < 2; np++) {
            int r = warp_n * 32 + np * 16 + brow;
            LDSM4(bH[2 * np][0], bH[2 * np][1], bH[2 * np + 1][0], bH[2 * np + 1][1],
                  BH + swz(r, q0 + bqad));
        }
        #pragma unroll
        for (int mt = 0; mt < 4; mt++)
            #pragma unroll
            for (int nt = 0; nt < 4; nt++) mma16816(acc[mt][nt], aH[mt], bH[nt]);
        {
            uint32_t bL[4][2];
            #pragma unroll
            for (int np = 0; np < 2; np++) {
                int r = warp_n * 32 + np * 16 + brow;
                LDSM4(bL[2 * np][0], bL[2 * np][1], bL[2 * np + 1][0], bL[2 * np + 1][1],
                      BL + swz(r, q0 + bqad));
            }
            #pragma unroll
            for (int mt = 0; mt < 4; mt++)
                #pragma unroll
                for (int nt = 0; nt < 4; nt++) mma16816(acc[mt][nt], aH[mt], bL[nt]);
        }
        {
            uint32_t aL[4][4];
            #pragma unroll
            for (int mt = 0; mt < 4; mt++) {
                int r = warp_m * 64 + mt * 16 + arow;
                LDSM4(aL[mt][0], aL[mt][1], aL[mt][2], aL[mt][3], AL + swz(r, q0 + aqad));
            }
            #pragma unroll
            for (int mt = 0; mt < 4; mt++)
                #pragma unroll
                for (int nt = 0; nt < 4; nt++) mma16816(acc[mt][nt], aL[mt], bH[nt]);
        }
    }
}

// Full 128x128x256 tile, 3-stage cp.async ring, one __syncthreads per chunk.
__device__ __forceinline__ void gemm_tile(float acc[4][4][4], char* smem,
                                          const __nv_bfloat16* ah, const __nv_bfloat16* al,
                                          const __nv_bfloat16* bh, const __nv_bfloat16* bl,
                                          int strideA, int strideB,
                                          int warp_m, int warp_n, int lane, int tid) {
    const uint32_t sbase = smem_u32(smem);
    fill_buf(sbase,             ah, al, bh, bl, strideA, strideB, 0,  tid);
    CP_COMMIT();
    fill_buf(sbase + BUF_BYTES, ah, al, bh, bl, strideA, strideB, 32, tid);
    CP_COMMIT();
    #pragma unroll 1
    for (int c = 0; c < 8; c++) {
        if (c < 7) { CP_WAIT1(); } else { CP_WAIT0(); }
        __syncthreads();
        // fill(c+2) targets buffer (c-1)%3; barrier above guarantees everyone
        // finished compute(c-1), so the overwrite is safe.
        if (c < 6) {
            fill_buf(sbase + ((c + 2) % 3) * BUF_BYTES, ah, al, bh, bl,
                     strideA, strideB, (c + 2) * 32, tid);
            CP_COMMIT();
        }
        compute_chunk(acc, sbase + (c % 3) * BUF_BYTES, warp_m, warp_n, lane);
    }
}

// ---------------------------------------------------------------------------
// Prep: split X and W^T into bf16 hi/lo planes.
// ---------------------------------------------------------------------------
__global__ __launch_bounds__(256) void prep_split_x(const float* __restrict__ X) {
    int idx = blockIdx.x * 256 + threadIdx.x;          // 1M float4 groups
    float4 v = reinterpret_cast<const float4*>(X)[idx];
    __nv_bfloat16 h0 = __float2bfloat16(v.x), h1 = __float2bfloat16(v.y);
    __nv_bfloat16 h2 = __float2bfloat16(v.z), h3 = __float2bfloat16(v.w);
    __nv_bfloat16 l0 = __float2bfloat16(v.x - __bfloat162float(h0));
    __nv_bfloat16 l1 = __float2bfloat16(v.y - __bfloat162float(h1));
    __nv_bfloat16 l2 = __float2bfloat16(v.z - __bfloat162float(h2));
    __nv_bfloat16 l3 = __float2bfloat16(v.w - __bfloat162float(h3));
    reinterpret_cast<uint2*>(g_Xhi)[idx] =
        make_uint2(bfu(h0) | (bfu(h1) << 16), bfu(h2) | (bfu(h3) << 16));
    reinterpret_cast<uint2*>(g_Xlo)[idx] =
        make_uint2(bfu(l0) | (bfu(l1) << 16), bfu(l2) | (bfu(l3) << 16));
}

__global__ __launch_bounds__(256) void prep_split_w(const float* __restrict__ Wu,
                                                    const float* __restrict__ Wl) {
    int idx = blockIdx.x * 256 + threadIdx.x;          // 131072 elements
    int w = idx >> 16, rem = idx & 65535;
    int n = rem >> 8, k = rem & 255;
    float v = (w ? Wl : Wu)[k * 256 + n];
    __nv_bfloat16 h = __float2bfloat16(v);
    __nv_bfloat16 l = __float2bfloat16(v - __bfloat162float(h));
    g_Wthi[idx] = h;
    g_Wtlo[idx] = l;
}

// ---------------------------------------------------------------------------
// Stage 1: Y = X @ [Wu | Wl].  grid (128, 4).
// ---------------------------------------------------------------------------
__global__ __launch_bounds__(256, 2) void stage1_xw() {
    extern __shared__ char smem[];
    const int tid = threadIdx.x, lane = tid & 31, wid = tid >> 5;
    const int warp_m = wid >> 2, warp_n = wid & 3;
    const int m0 = blockIdx.x * 128;
    const int ny = blockIdx.y;                 // 0..3
    const int w = ny >> 1;

    const __nv_bfloat16* ah = g_Xhi + (size_t)m0 * 256;
    const __nv_bfloat16* al = g_Xlo + (size_t)m0 * 256;
    const __nv_bfloat16* bh = g_Wthi + (size_t)w * 65536 + (size_t)(ny & 1) * 128 * 256;
    const __nv_bfloat16* bl = g_Wtlo + (size_t)w * 65536 + (size_t)(ny & 1) * 128 * 256;

    float acc[4][4][4] = {};
    gemm_tile(acc, smem, ah, al, bh, bl, 256, 256, warp_m, warp_n, lane, tid);

    const int g = lane >> 2, c2 = (lane & 3) * 2;
    #pragma unroll
    for (int mt = 0; mt < 4; mt++) {
        #pragma unroll
        for (int nt = 0; nt < 4; nt++) {
            const int m = m0 + warp_m * 64 + mt * 16 + g;
            const int n = ny * 128 + warp_n * 32 + nt * 8 + c2;
            #pragma unroll
            for (int h = 0; h < 2; h++) {
                float x = acc[mt][nt][2 * h];
                float y = acc[mt][nt][2 * h + 1];
                __nv_bfloat16 xh = __float2bfloat16(x), yh = __float2bfloat16(y);
                __nv_bfloat16 xl = __float2bfloat16(x - __bfloat162float(xh));
                __nv_bfloat16 yl = __float2bfloat16(y - __bfloat162float(yh));
                size_t off = (size_t)(m + 8 * h) * 512 + n;
                *(uint32_t*)(g_Yhi + off) = bfu(xh) | (bfu(yh) << 16);
                *(uint32_t*)(g_Ylo + off) = bfu(xl) | (bfu(yl) << 16);
            }
        }
    }
}

// ---------------------------------------------------------------------------
// Stage 2: adj[b,p,q] = dot(Ysel[b,p,:], X[b,q,:]) + bias_sel.
// grid (72, 16): 36 upper-triangle tile-passes + 36 lower — diagonal tiles are
// handled by TWO CTAs (one per pass) for uniform per-CTA work.
// ---------------------------------------------------------------------------
__global__ __launch_bounds__(256, 2) void stage2_adj(const float* __restrict__ bu,
                                                     const float* __restrict__ bl,
                                                     float* __restrict__ out) {
    extern __shared__ char smem[];
    const int tid = threadIdx.x, lane = tid & 31, wid = tid >> 5;
    const int warp_m = wid >> 2, warp_n = wid & 3;
    const int b = blockIdx.y;

    int t = blockIdx.x;                 // 0..71
    const int pass = (t >= 36) ? 1 : 0;
    int i = pass ? t - 36 : t;
    int r0 = 0;
    while (i >= 8 - r0) { i -= 8 - r0; r0++; }
    const int lo = r0, hi = r0 + i;     // lo <= hi
    const int pt = pass ? hi : lo;
    const int qt = pass ? lo : hi;
    const int p0 = pt * 128, q0 = qt * 128;

    const float bias = pass ? __ldg(bl) : __ldg(bu);
    const __nv_bfloat16* xh = g_Xhi + (size_t)(b * NPTS + q0) * 256;
    const __nv_bfloat16* xl = g_Xlo + (size_t)(b * NPTS + q0) * 256;
    const __nv_bfloat16* yh = g_Yhi + (size_t)(b * NPTS + p0) * 512 + pass * 256;
    const __nv_bfloat16* yl = g_Ylo + (size_t)(b * NPTS + p0) * 512 + pass * 256;

    float acc[4][4][4] = {};
    gemm_tile(acc, smem, yh, yl, xh, xl, 512, 256, warp_m, warp_n, lane, tid);

    const int g = lane >> 2, c2 = (lane & 3) * 2;
    #pragma unroll
    for (int mt = 0; mt < 4; mt++) {
        #pragma unroll
        for (int nt = 0; nt < 4; nt++) {
            const int q = q0 + warp_n * 32 + nt * 8 + c2;
            #pragma unroll
            for (int h = 0; h < 2; h++) {
                const int p = p0 + warp_m * 64 + mt * 16 + g + 8 * h;
                float* dst = out + ((size_t)b << 20) + ((size_t)p << 10) + q;
                float v0 = acc[mt][nt][2 * h] + bias;
                float v1 = acc[mt][nt][2 * h + 1] + bias;
                if (pt != qt) {
                    *(float2*)dst = make_float2(v0, v1);
                } else if (pass == 0) {
                    if (p <= q)     dst[0] = v0;
                    if (p <= q + 1) dst[1] = v1;
                } else {
                    if (p > q)      dst[0] = v0;
                    if (p > q + 1)  dst[1] = v1;
                }
            }
        }
    }
}

// ---------------------------------------------------------------------------
// kernel_launch
// ---------------------------------------------------------------------------
extern "C" void kernel_launch(void* const* d_in, const int* in_sizes, int n_in,
                              void* d_out, int out_size) {
    const float* feats = (const float*)d_in[0];
    const float* Wu    = (const float*)d_in[1];
    const float* bu    = (const float*)d_in[2];
    const float* Wl    = (const float*)d_in[3];
    const float* bl    = (const float*)d_in[4];
    float* out = (float*)d_out;

    cudaFuncSetAttribute(stage1_xw,  cudaFuncAttributeMaxDynamicSharedMemorySize, SMEM_TOTAL);
    cudaFuncSetAttribute(stage2_adj, cudaFuncAttributeMaxDynamicSharedMemorySize, SMEM_TOTAL);

    prep_split_x<<<4096, 256>>>(feats);
    prep_split_w<<<512, 256>>>(Wu, Wl);
    stage1_xw<<<dim3(128, 4), 256, SMEM_TOTAL>>>();
    stage2_adj<<<dim3(72, 16), 256, SMEM_TOTAL>>>(bu, bl, out);
}

// round 6
// speedup vs baseline: 3.3999x; 1.1749x over previous
#include <cuda_runtime.h>
#include <cuda_bf16.h>
#include <cstdint>

#define NPTS 1024
#define DIM  256

// ---------------------------------------------------------------------------
// Scratch (__device__ globals). All stored PRE-SWIZZLED as contiguous 8KB
// tile-chunks: block = 128 rows x 32 cols(bf16) = 8KB, row r / quad q at
// offset swz(r,q). Layouts:
//   X planes: [128 rowblocks][8 kchunks][8192B]
//   W planes: [2 w][2 nblocks][8 kchunks][8192B]
//   Y planes: [2 w][128 rowblocks][8 kchunks][8192B]
// ---------------------------------------------------------------------------
__device__ __align__(16) __nv_bfloat16 g_Xhi[16384 * 256];
__device__ __align__(16) __nv_bfloat16 g_Xlo[16384 * 256];
__device__ __align__(16) __nv_bfloat16 g_Wthi[2 * 256 * 256];
__device__ __align__(16) __nv_bfloat16 g_Wtlo[2 * 256 * 256];
__device__ __align__(16) __nv_bfloat16 g_Yhi[2 * 16384 * 256];
__device__ __align__(16) __nv_bfloat16 g_Ylo[2 * 16384 * 256];

#define TILE_BYTES 8192
#define BLOCK_BYTES 65536             // 8 kchunks per 128-row block
#define BUF_BYTES  (4 * TILE_BYTES)   // Ah, Al, Bh, Bl = 32768
#define STAGES 3
#define SMEM_TOTAL (STAGES * BUF_BYTES)   // 98304; x2 CTAs = 192K <= 228K/SM

__device__ __forceinline__ uint32_t smem_u32(const void* p) {
    uint32_t a;
    asm("{ .reg .u64 t; cvta.to.shared.u64 t, %1; cvt.u32.u64 %0, t; }" : "=r"(a) : "l"(p));
    return a;
}
__device__ __forceinline__ uint32_t bfu(__nv_bfloat16 v) {
    return (uint32_t)__bfloat16_as_ushort(v);
}
__device__ __forceinline__ uint32_t swz(int r, int q) {
    return (uint32_t)(r * 64 + (((q + (r >> 1)) & 3) << 4));
}

// HMMA: D += A(16x16 bf16, row) * B(16x8 bf16, col), fp32 acc.
__device__ __forceinline__ void mma16816(float* d, const uint32_t* a, const uint32_t* b) {
    asm volatile(
        "mma.sync.aligned.m16n8k16.row.col.f32.bf16.bf16.f32 "
        "{%0,%1,%2,%3}, {%4,%5,%6,%7}, {%8,%9}, {%0,%1,%2,%3};\n"
        : "+f"(d[0]), "+f"(d[1]), "+f"(d[2]), "+f"(d[3])
        : "r"(a[0]), "r"(a[1]), "r"(a[2]), "r"(a[3]), "r"(b[0]), "r"(b[1]));
}
#define LDSM4(r0, r1, r2, r3, addr) \
    asm volatile("ldmatrix.sync.aligned.m8n8.x4.shared.b16 {%0,%1,%2,%3}, [%4];" \
        : "=r"(r0), "=r"(r1), "=r"(r2), "=r"(r3) : "r"(addr))

#define MBAR_INIT(a, c) \
    asm volatile("mbarrier.init.shared.b64 [%0], %1;" :: "r"(a), "r"(c) : "memory")
#define MBAR_EXPECT(a, n) \
    asm volatile("mbarrier.arrive.expect_tx.shared.b64 _, [%0], %1;" :: "r"(a), "r"(n) : "memory")
#define MBAR_WAIT(a, ph) do { \
    asm volatile("{\n\t.reg .pred P;\n\tWL_%=:\n\t" \
        "mbarrier.try_wait.parity.acquire.cta.shared::cta.b64 P, [%0], %1, 0x989680;\n\t" \
        "@P bra.uni WD_%=;\n\tbra.uni WL_%=;\n\tWD_%=:\n\t}" \
        :: "r"(a), "r"(ph) : "memory"); } while (0)

__device__ __forceinline__ void bulk_cp8k(uint32_t dst, const char* src, uint32_t mbar) {
    asm volatile(
        "cp.async.bulk.shared::cluster.global.mbarrier::complete_tx::bytes [%0], [%1], %2, [%3];"
        :: "r"(dst), "l"(src), "r"(8192u), "r"(mbar) : "memory");
}

// Issue one buffer fill: 4 x 8KB engine copies + expect_tx. ONE thread.
__device__ __forceinline__ void issue_fill(uint32_t sbase, uint32_t mbar,
                                           const char* ah, const char* al,
                                           const char* bh, const char* bl, int c) {
    const uint32_t dst = sbase + (uint32_t)(c % 3) * BUF_BYTES;
    const uint32_t off = (uint32_t)c * TILE_BYTES;
    MBAR_EXPECT(mbar, BUF_BYTES);
    bulk_cp8k(dst,                  ah + off, mbar);
    bulk_cp8k(dst + TILE_BYTES,     al + off, mbar);
    bulk_cp8k(dst + 2 * TILE_BYTES, bh + off, mbar);
    bulk_cp8k(dst + 3 * TILE_BYTES, bl + off, mbar);
}

// One K-chunk: acc += Ah*Bh + Ah*Bl + Al*Bh. Warp tile 64x32, ldmatrix frags.
__device__ __forceinline__ void compute_chunk(float acc[4][4][4], uint32_t bufu,
                                              int warp_m, int warp_n, int lane) {
    const int arow = (lane & 7) + ((lane >> 3) & 1) * 8;
    const int aqad = lane >> 4;
    const int brow = (lane & 7) + ((lane >> 4) & 1) * 8;
    const int bqad = (lane >> 3) & 1;
    const uint32_t AH = bufu, AL = bufu + TILE_BYTES;
    const uint32_t BH = bufu + 2 * TILE_BYTES, BL = bufu + 3 * TILE_BYTES;

    #pragma unroll
    for (int ks = 0; ks < 2; ks++) {
        const int q0 = 2 * ks;
        uint32_t aH[4][4], bH[4][2];
        #pragma unroll
        for (int mt = 0; mt < 4; mt++) {
            int r = warp_m * 64 + mt * 16 + arow;
            LDSM4(aH[mt][0], aH[mt][1], aH[mt][2], aH[mt][3], AH + swz(r, q0 + aqad));
        }
        #pragma unroll
        for (int np = 0; np < 2; np++) {
            int r = warp_n * 32 + np * 16 + brow;
            LDSM4(bH[2 * np][0], bH[2 * np][1], bH[2 * np + 1][0], bH[2 * np + 1][1],
                  BH + swz(r, q0 + bqad));
        }
        #pragma unroll
        for (int mt = 0; mt < 4; mt++)
            #pragma unroll
            for (int nt = 0; nt < 4; nt++) mma16816(acc[mt][nt], aH[mt], bH[nt]);
        {
            uint32_t bL[4][2];
            #pragma unroll
            for (int np = 0; np < 2; np++) {
                int r = warp_n * 32 + np * 16 + brow;
                LDSM4(bL[2 * np][0], bL[2 * np][1], bL[2 * np + 1][0], bL[2 * np + 1][1],
                      BL + swz(r, q0 + bqad));
            }
            #pragma unroll
            for (int mt = 0; mt < 4; mt++)
                #pragma unroll
                for (int nt = 0; nt < 4; nt++) mma16816(acc[mt][nt], aH[mt], bL[nt]);
        }
        {
            uint32_t aL[4][4];
            #pragma unroll
            for (int mt = 0; mt < 4; mt++) {
                int r = warp_m * 64 + mt * 16 + arow;
                LDSM4(aL[mt][0], aL[mt][1], aL[mt][2], aL[mt][3], AL + swz(r, q0 + aqad));
            }
            #pragma unroll
            for (int mt = 0; mt < 4; mt++)
                #pragma unroll
                for (int nt = 0; nt < 4; nt++) mma16816(acc[mt][nt], aL[mt], bH[nt]);
        }
    }
}

// 128x128x256 tile: 3-stage bulk-copy ring, one barrier + one mbar-wait/chunk.
__device__ __forceinline__ void gemm_tile(float acc[4][4][4], char* smem,
                                          const uint64_t* mbars_sh,
                                          const char* ah, const char* al,
                                          const char* bh, const char* bl,
                                          int warp_m, int warp_n, int lane, int tid) {
    const uint32_t sbase = smem_u32(smem);
    uint32_t mb[3];
    mb[0] = smem_u32(&mbars_sh[0]);
    mb[1] = smem_u32(&mbars_sh[1]);
    mb[2] = smem_u32(&mbars_sh[2]);
    if (tid == 0) {
        issue_fill(sbase, mb[0], ah, al, bh, bl, 0);
        issue_fill(sbase, mb[1], ah, al, bh, bl, 1);
    }
    #pragma unroll 1
    for (int c = 0; c < 8; c++) {
        if (c >= 1) __syncthreads();             // everyone done reading buf (c-1)%3
        if (tid == 0 && c + 2 < 8)
            issue_fill(sbase, mb[(c + 2) % 3], ah, al, bh, bl, c + 2);
        MBAR_WAIT(mb[c % 3], (c / 3) & 1);
        compute_chunk(acc, sbase + (uint32_t)(c % 3) * BUF_BYTES, warp_m, warp_n, lane);
    }
}

// ---------------------------------------------------------------------------
// Prep: split into bf16 hi/lo planes, writing the PRE-SWIZZLED tiled layout.
// ---------------------------------------------------------------------------
__global__ __launch_bounds__(256) void prep_split_x(const float* __restrict__ X) {
    int idx = blockIdx.x * 256 + threadIdx.x;      // 524288 groups of 8 elems
    int row = idx >> 5, cg = idx & 31;
    int kc = cg >> 2, q = cg & 3;
    const float* src = X + (size_t)row * 256 + cg * 8;
    uint32_t hw[4], lw[4];
    #pragma unroll
    for (int t = 0; t < 4; t++) {
        float a = src[2 * t], b = src[2 * t + 1];
        __nv_bfloat16 ah = __float2bfloat16(a), bh = __float2bfloat16(b);
        __nv_bfloat16 al = __float2bfloat16(a - __bfloat162float(ah));
        __nv_bfloat16 bl = __float2bfloat16(b - __bfloat162float(bh));
        hw[t] = bfu(ah) | (bfu(bh) << 16);
        lw[t] = bfu(al) | (bfu(bl) << 16);
    }
    size_t off = ((size_t)(row >> 7) * 8 + kc) * TILE_BYTES + swz(row & 127, q);
    *reinterpret_cast<uint4*>((char*)g_Xhi + off) = make_uint4(hw[0], hw[1], hw[2], hw[3]);
    *reinterpret_cast<uint4*>((char*)g_Xlo + off) = make_uint4(lw[0], lw[1], lw[2], lw[3]);
}

__global__ __launch_bounds__(256) void prep_split_w(const float* __restrict__ Wu,
                                                    const float* __restrict__ Wl) {
    int idx = blockIdx.x * 256 + threadIdx.x;      // 16384: (w, n, kg)
    int w = idx >> 13, rem = idx & 8191;
    int n = rem >> 5, kg = rem & 31;
    int kc = kg >> 2, q = kg & 3;
    const float* src = (w ? Wl : Wu);
    uint32_t hw[4], lw[4];
    #pragma unroll
    for (int t = 0; t < 4; t++) {
        float a = src[(size_t)(kg * 8 + 2 * t) * 256 + n];
        float b = src[(size_t)(kg * 8 + 2 * t + 1) * 256 + n];
        __nv_bfloat16 ah = __float2bfloat16(a), bh = __float2bfloat16(b);
        __nv_bfloat16 al = __float2bfloat16(a - __bfloat162float(ah));
        __nv_bfloat16 bl = __float2bfloat16(b - __bfloat162float(bh));
        hw[t] = bfu(ah) | (bfu(bh) << 16);
        lw[t] = bfu(al) | (bfu(bl) << 16);
    }
    size_t off = ((size_t)(w * 2 + (n >> 7)) * 8 + kc) * TILE_BYTES + swz(n & 127, q);
    *reinterpret_cast<uint4*>((char*)g_Wthi + off) = make_uint4(hw[0], hw[1], hw[2], hw[3]);
    *reinterpret_cast<uint4*>((char*)g_Wtlo + off) = make_uint4(lw[0], lw[1], lw[2], lw[3]);
}

// ---------------------------------------------------------------------------
// Stage 1: Y = X @ [Wu | Wl].  grid (128, 4). Epilogue writes swizzled Y.
// ---------------------------------------------------------------------------
__global__ __launch_bounds__(256, 2) void stage1_xw() {
    extern __shared__ char smem[];
    __shared__ __align__(8) uint64_t mbars[3];
    const int tid = threadIdx.x, lane = tid & 31, wid = tid >> 5;
    const int warp_m = wid >> 2, warp_n = wid & 3;
    const int mb_ = blockIdx.x;               // 0..127
    const int ny = blockIdx.y;                // 0..3
    const int w = ny >> 1, nb = ny & 1;

    if (tid == 0) { MBAR_INIT(smem_u32(&mbars[0]), 1); MBAR_INIT(smem_u32(&mbars[1]), 1);
                    MBAR_INIT(smem_u32(&mbars[2]), 1); }
    __syncthreads();

    const char* ah = (const char*)g_Xhi + (size_t)mb_ * BLOCK_BYTES;
    const char* al = (const char*)g_Xlo + (size_t)mb_ * BLOCK_BYTES;
    const char* bh = (const char*)g_Wthi + (size_t)(w * 2 + nb) * BLOCK_BYTES;
    const char* bl = (const char*)g_Wtlo + (size_t)(w * 2 + nb) * BLOCK_BYTES;

    float acc[4][4][4] = {};
    gemm_tile(acc, smem, mbars, ah, al, bh, bl, warp_m, warp_n, lane, tid);

    // Epilogue: split fp32 -> bf16 hi/lo, write into swizzled tiled Y layout.
    const int g = lane >> 2, c2 = (lane & 3) * 2;
    #pragma unroll
    for (int mt = 0; mt < 4; mt++) {
        #pragma unroll
        for (int nt = 0; nt < 4; nt++) {
            const int nl = nb * 128 + warp_n * 32 + nt * 8 + c2;   // 0..255 within w
            const int kc = nl >> 5, q = (nl >> 3) & 3, e = nl & 7;
            #pragma unroll
            for (int h = 0; h < 2; h++) {
                const int r = warp_m * 64 + mt * 16 + g + 8 * h;   // row in block
                float x = acc[mt][nt][2 * h];
                float y = acc[mt][nt][2 * h + 1];
                __nv_bfloat16 xh = __float2bfloat16(x), yh = __float2bfloat16(y);
                __nv_bfloat16 xl = __float2bfloat16(x - __bfloat162float(xh));
                __nv_bfloat16 yl = __float2bfloat16(y - __bfloat162float(yh));
                size_t off = ((size_t)(w * 128 + mb_) * 8 + kc) * TILE_BYTES
                           + swz(r, q) + e * 2;
                *(uint32_t*)((char*)g_Yhi + off) = bfu(xh) | (bfu(yh) << 16);
                *(uint32_t*)((char*)g_Ylo + off) = bfu(xl) | (bfu(yl) << 16);
            }
        }
    }
}

// ---------------------------------------------------------------------------
// Stage 2: adj[b,p,q] = dot(Ysel[b,p,:], X[b,q,:]) + bias_sel.
// grid (72, 16): 36 upper + 36 lower tile-passes; diagonal tiles split.
// ---------------------------------------------------------------------------
__global__ __launch_bounds__(256, 2) void stage2_adj(const float* __restrict__ bu,
                                                     const float* __restrict__ bl,
                                                     float* __restrict__ out) {
    extern __shared__ char smem[];
    __shared__ __align__(8) uint64_t mbars[3];
    const int tid = threadIdx.x, lane = tid & 31, wid = tid >> 5;
    const int warp_m = wid >> 2, warp_n = wid & 3;
    const int b = blockIdx.y;

    int t = blockIdx.x;                 // 0..71
    const int pass = (t >= 36) ? 1 : 0;
    int i = pass ? t - 36 : t;
    int r0 = 0;
    while (i >= 8 - r0) { i -= 8 - r0; r0++; }
    const int lo = r0, hi = r0 + i;     // lo <= hi
    const int pt = pass ? hi : lo;
    const int qt = pass ? lo : hi;
    const int p0 = pt * 128, q0 = qt * 128;

    if (tid == 0) { MBAR_INIT(smem_u32(&mbars[0]), 1); MBAR_INIT(smem_u32(&mbars[1]), 1);
                    MBAR_INIT(smem_u32(&mbars[2]), 1); }
    __syncthreads();

    const float bias = pass ? __ldg(bl) : __ldg(bu);
    const char* yh = (const char*)g_Yhi + (size_t)(pass * 128 + b * 8 + pt) * BLOCK_BYTES;
    const char* yl = (const char*)g_Ylo + (size_t)(pass * 128 + b * 8 + pt) * BLOCK_BYTES;
    const char* xh = (const char*)g_Xhi + (size_t)(b * 8 + qt) * BLOCK_BYTES;
    const char* xl = (const char*)g_Xlo + (size_t)(b * 8 + qt) * BLOCK_BYTES;

    float acc[4][4][4] = {};
    gemm_tile(acc, smem, mbars, yh, yl, xh, xl, warp_m, warp_n, lane, tid);

    const int g = lane >> 2, c2 = (lane & 3) * 2;
    #pragma unroll
    for (int mt = 0; mt < 4; mt++) {
        #pragma unroll
        for (int nt = 0; nt < 4; nt++) {
            const int q = q0 + warp_n * 32 + nt * 8 + c2;
            #pragma unroll
            for (int h = 0; h < 2; h++) {
                const int p = p0 + warp_m * 64 + mt * 16 + g + 8 * h;
                float* dst = out + ((size_t)b << 20) + ((size_t)p << 10) + q;
                float v0 = acc[mt][nt][2 * h] + bias;
                float v1 = acc[mt][nt][2 * h + 1] + bias;
                if (pt != qt) {
                    *(float2*)dst = make_float2(v0, v1);
                } else if (pass == 0) {
                    if (p <= q)     dst[0] = v0;
                    if (p <= q + 1) dst[1] = v1;
                } else {
                    if (p > q)      dst[0] = v0;
                    if (p > q + 1)  dst[1] = v1;
                }
            }
        }
    }
}

// ---------------------------------------------------------------------------
// kernel_launch
// ---------------------------------------------------------------------------
extern "C" void kernel_launch(void* const* d_in, const int* in_sizes, int n_in,
                              void* d_out, int out_size) {
    const float* feats = (const float*)d_in[0];
    const float* Wu    = (const float*)d_in[1];
    const float* bu    = (const float*)d_in[2];
    const float* Wl    = (const float*)d_in[3];
    const float* bl    = (const float*)d_in[4];
    float* out = (float*)d_out;

    cudaFuncSetAttribute(stage1_xw,  cudaFuncAttributeMaxDynamicSharedMemorySize, SMEM_TOTAL);
    cudaFuncSetAttribute(stage2_adj, cudaFuncAttributeMaxDynamicSharedMemorySize, SMEM_TOTAL);

    prep_split_x<<<2048, 256>>>(feats);
    prep_split_w<<<64, 256>>>(Wu, Wl);
    stage1_xw<<<dim3(128, 4), 256, SMEM_TOTAL>>>();
    stage2_adj<<<dim3(72, 16), 256, SMEM_TOTAL>>>(bu, bl, out);
}

// round 7
// speedup vs baseline: 3.5371x; 1.0404x over previous
#include <cuda_runtime.h>
#include <cuda_bf16.h>
#include <cstdint>

#define NPTS 1024
#define DIM  256

// ---------------------------------------------------------------------------
// Scratch (__device__ globals). All stored PRE-SWIZZLED as contiguous 8KB
// tile-chunks: block = 128 rows x 32 cols(bf16) = 8KB, row r / quad q at
// offset swz(r,q). Layouts:
//   X planes: [128 rowblocks][8 kchunks][8192B]
//   W planes: [2 w][2 nblocks][8 kchunks][8192B]
//   Y planes: [2 w][128 rowblocks][8 kchunks][8192B]
// ---------------------------------------------------------------------------
__device__ __align__(16) __nv_bfloat16 g_Xhi[16384 * 256];
__device__ __align__(16) __nv_bfloat16 g_Xlo[16384 * 256];
__device__ __align__(16) __nv_bfloat16 g_Wthi[2 * 256 * 256];
__device__ __align__(16) __nv_bfloat16 g_Wtlo[2 * 256 * 256];
__device__ __align__(16) __nv_bfloat16 g_Yhi[2 * 16384 * 256];
__device__ __align__(16) __nv_bfloat16 g_Ylo[2 * 16384 * 256];

#define TILE_BYTES 8192
#define BLOCK_BYTES 65536             // 8 kchunks per 128-row block
#define BUF_BYTES  (4 * TILE_BYTES)   // Ah, Al, Bh, Bl = 32768
#define STAGES 3
#define SMEM_TOTAL (STAGES * BUF_BYTES)   // 98304; x2 CTAs = 192K <= 228K/SM

__device__ __forceinline__ uint32_t smem_u32(const void* p) {
    uint32_t a;
    asm("{ .reg .u64 t; cvta.to.shared.u64 t, %1; cvt.u32.u64 %0, t; }" : "=r"(a) : "l"(p));
    return a;
}
__device__ __forceinline__ uint32_t bfu(__nv_bfloat16 v) {
    return (uint32_t)__bfloat16_as_ushort(v);
}
__device__ __forceinline__ uint32_t swz(int r, int q) {
    return (uint32_t)(r * 64 + (((q + (r >> 1)) & 3) << 4));
}

// HMMA: D += A(16x16 bf16, row) * B(16x8 bf16, col), fp32 acc.
__device__ __forceinline__ void mma16816(float* d, const uint32_t* a, const uint32_t* b) {
    asm volatile(
        "mma.sync.aligned.m16n8k16.row.col.f32.bf16.bf16.f32 "
        "{%0,%1,%2,%3}, {%4,%5,%6,%7}, {%8,%9}, {%0,%1,%2,%3};\n"
        : "+f"(d[0]), "+f"(d[1]), "+f"(d[2]), "+f"(d[3])
        : "r"(a[0]), "r"(a[1]), "r"(a[2]), "r"(a[3]), "r"(b[0]), "r"(b[1]));
}
#define LDSM4(r0, r1, r2, r3, addr) \
    asm volatile("ldmatrix.sync.aligned.m8n8.x4.shared.b16 {%0,%1,%2,%3}, [%4];" \
        : "=r"(r0), "=r"(r1), "=r"(r2), "=r"(r3) : "r"(addr))

#define MBAR_INIT(a, c) \
    asm volatile("mbarrier.init.shared.b64 [%0], %1;" :: "r"(a), "r"(c) : "memory")
#define MBAR_EXPECT(a, n) \
    asm volatile("mbarrier.arrive.expect_tx.shared.b64 _, [%0], %1;" :: "r"(a), "r"(n) : "memory")
#define MBAR_ARRIVE(a) \
    asm volatile("mbarrier.arrive.release.cta.shared.b64 _, [%0];" :: "r"(a) : "memory")
#define MBAR_WAIT(a, ph) do { \
    asm volatile("{\n\t.reg .pred P;\n\tWL_%=:\n\t" \
        "mbarrier.try_wait.parity.acquire.cta.shared::cta.b64 P, [%0], %1, 0x989680;\n\t" \
        "@P bra.uni WD_%=;\n\tbra.uni WL_%=;\n\tWD_%=:\n\t}" \
        :: "r"(a), "r"(ph) : "memory"); } while (0)
#define FENCE_ASYNC() asm volatile("fence.proxy.async.shared::cta;" ::: "memory")

__device__ __forceinline__ void bulk_cp8k(uint32_t dst, const char* src, uint32_t mbar) {
    asm volatile(
        "cp.async.bulk.shared::cluster.global.mbarrier::complete_tx::bytes [%0], [%1], %2, [%3];"
        :: "r"(dst), "l"(src), "r"(8192u), "r"(mbar) : "memory");
}

// Issue one buffer fill: 4 x 8KB engine copies + expect_tx. ONE thread.
__device__ __forceinline__ void issue_fill(uint32_t sbase, uint32_t mbar,
                                           const char* ah, const char* al,
                                           const char* bh, const char* bl, int c) {
    const uint32_t dst = sbase + (uint32_t)(c % 3) * BUF_BYTES;
    const uint32_t off = (uint32_t)c * TILE_BYTES;
    MBAR_EXPECT(mbar, BUF_BYTES);
    bulk_cp8k(dst,                  ah + off, mbar);
    bulk_cp8k(dst + TILE_BYTES,     al + off, mbar);
    bulk_cp8k(dst + 2 * TILE_BYTES, bh + off, mbar);
    bulk_cp8k(dst + 3 * TILE_BYTES, bl + off, mbar);
}

// One K-chunk: acc += Ah*Bh + Ah*Bl + Al*Bh. Warp tile 64x32, ldmatrix frags.
__device__ __forceinline__ void compute_chunk(float acc[4][4][4], uint32_t bufu,
                                              int warp_m, int warp_n, int lane) {
    const int arow = (lane & 7) + ((lane >> 3) & 1) * 8;
    const int aqad = lane >> 4;
    const int brow = (lane & 7) + ((lane >> 4) & 1) * 8;
    const int bqad = (lane >> 3) & 1;
    const uint32_t AH = bufu, AL = bufu + TILE_BYTES;
    const uint32_t BH = bufu + 2 * TILE_BYTES, BL = bufu + 3 * TILE_BYTES;

    #pragma unroll
    for (int ks = 0; ks < 2; ks++) {
        const int q0 = 2 * ks;
        uint32_t aH[4][4], bH[4][2];
        #pragma unroll
        for (int mt = 0; mt < 4; mt++) {
            int r = warp_m * 64 + mt * 16 + arow;
            LDSM4(aH[mt][0], aH[mt][1], aH[mt][2], aH[mt][3], AH + swz(r, q0 + aqad));
        }
        #pragma unroll
        for (int np = 0; np < 2; np++) {
            int r = warp_n * 32 + np * 16 + brow;
            LDSM4(bH[2 * np][0], bH[2 * np][1], bH[2 * np + 1][0], bH[2 * np + 1][1],
                  BH + swz(r, q0 + bqad));
        }
        #pragma unroll
        for (int mt = 0; mt < 4; mt++)
            #pragma unroll
            for (int nt = 0; nt < 4; nt++) mma16816(acc[mt][nt], aH[mt], bH[nt]);
        {
            uint32_t bL[4][2];
            #pragma unroll
            for (int np = 0; np < 2; np++) {
                int r = warp_n * 32 + np * 16 + brow;
                LDSM4(bL[2 * np][0], bL[2 * np][1], bL[2 * np + 1][0], bL[2 * np + 1][1],
                      BL + swz(r, q0 + bqad));
            }
            #pragma unroll
            for (int mt = 0; mt < 4; mt++)
                #pragma unroll
                for (int nt = 0; nt < 4; nt++) mma16816(acc[mt][nt], aH[mt], bL[nt]);
        }
        {
            uint32_t aL[4][4];
            #pragma unroll
            for (int mt = 0; mt < 4; mt++) {
                int r = warp_m * 64 + mt * 16 + arow;
                LDSM4(aL[mt][0], aL[mt][1], aL[mt][2], aL[mt][3], AL + swz(r, q0 + aqad));
            }
            #pragma unroll
            for (int mt = 0; mt < 4; mt++)
                #pragma unroll
                for (int nt = 0; nt < 4; nt++) mma16816(acc[mt][nt], aL[mt], bH[nt]);
        }
    }
}

// 128x128x256 tile: producer/consumer mbarrier ring, NO per-chunk syncthreads.
// full[i]: tx barrier (bulk-copy completion). empty[i]: 8 warp release-arrives.
__device__ __forceinline__ void gemm_tile(float acc[4][4][4], char* smem,
                                          const uint64_t* full_sh, const uint64_t* empty_sh,
                                          const char* ah, const char* al,
                                          const char* bh, const char* bl,
                                          int warp_m, int warp_n, int lane, int tid) {
    const uint32_t sbase = smem_u32(smem);
    uint32_t fb[3], eb[3];
    #pragma unroll
    for (int i = 0; i < 3; i++) { fb[i] = smem_u32(&full_sh[i]); eb[i] = smem_u32(&empty_sh[i]); }

    if (tid == 0) {
        issue_fill(sbase, fb[0], ah, al, bh, bl, 0);
        issue_fill(sbase, fb[1], ah, al, bh, bl, 1);
    }
    #pragma unroll 1
    for (int c = 0; c < 8; c++) {
        // Producer: refill buffer (c+2)%3 once compute(c-1) released it.
        if (tid == 0 && c + 2 < 8) {
            if (c >= 1) {
                MBAR_WAIT(eb[(c + 2) % 3], ((c - 1) / 3) & 1);
                FENCE_ASYNC();
            }
            issue_fill(sbase, fb[(c + 2) % 3], ah, al, bh, bl, c + 2);
        }
        // Consumer: wait data, compute, release buffer.
        MBAR_WAIT(fb[c % 3], (c / 3) & 1);
        compute_chunk(acc, sbase + (uint32_t)(c % 3) * BUF_BYTES, warp_m, warp_n, lane);
        if (lane == 0) MBAR_ARRIVE(eb[c % 3]);
    }
}

// ---------------------------------------------------------------------------
// Prep (merged): split X and W^T into bf16 hi/lo planes, pre-swizzled layout.
// grid.x = 2048 (X part) + 64 (W part).
// ---------------------------------------------------------------------------
__global__ __launch_bounds__(256) void prep_split(const float* __restrict__ X,
                                                  const float* __restrict__ Wu,
                                                  const float* __restrict__ Wl) {
    if (blockIdx.x < 2048) {
        int idx = blockIdx.x * 256 + threadIdx.x;      // 524288 groups of 8 elems
        int row = idx >> 5, cg = idx & 31;
        int kc = cg >> 2, q = cg & 3;
        const float* src = X + (size_t)row * 256 + cg * 8;
        uint32_t hw[4], lw[4];
        #pragma unroll
        for (int t = 0; t < 4; t++) {
            float a = src[2 * t], b = src[2 * t + 1];
            __nv_bfloat16 ah = __float2bfloat16(a), bh = __float2bfloat16(b);
            __nv_bfloat16 al = __float2bfloat16(a - __bfloat162float(ah));
            __nv_bfloat16 bl = __float2bfloat16(b - __bfloat162float(bh));
            hw[t] = bfu(ah) | (bfu(bh) << 16);
            lw[t] = bfu(al) | (bfu(bl) << 16);
        }
        size_t off = ((size_t)(row >> 7) * 8 + kc) * TILE_BYTES + swz(row & 127, q);
        *reinterpret_cast<uint4*>((char*)g_Xhi + off) = make_uint4(hw[0], hw[1], hw[2], hw[3]);
        *reinterpret_cast<uint4*>((char*)g_Xlo + off) = make_uint4(lw[0], lw[1], lw[2], lw[3]);
    } else {
        int idx = (blockIdx.x - 2048) * 256 + threadIdx.x;  // 16384: (w, n, kg)
        int w = idx >> 13, rem = idx & 8191;
        int n = rem >> 5, kg = rem & 31;
        int kc = kg >> 2, q = kg & 3;
        const float* src = (w ? Wl : Wu);
        uint32_t hw[4], lw[4];
        #pragma unroll
        for (int t = 0; t < 4; t++) {
            float a = src[(size_t)(kg * 8 + 2 * t) * 256 + n];
            float b = src[(size_t)(kg * 8 + 2 * t + 1) * 256 + n];
            __nv_bfloat16 ah = __float2bfloat16(a), bh = __float2bfloat16(b);
            __nv_bfloat16 al = __float2bfloat16(a - __bfloat162float(ah));
            __nv_bfloat16 bl = __float2bfloat16(b - __bfloat162float(bh));
            hw[t] = bfu(ah) | (bfu(bh) << 16);
            lw[t] = bfu(al) | (bfu(bl) << 16);
        }
        size_t off = ((size_t)(w * 2 + (n >> 7)) * 8 + kc) * TILE_BYTES + swz(n & 127, q);
        *reinterpret_cast<uint4*>((char*)g_Wthi + off) = make_uint4(hw[0], hw[1], hw[2], hw[3]);
        *reinterpret_cast<uint4*>((char*)g_Wtlo + off) = make_uint4(lw[0], lw[1], lw[2], lw[3]);
    }
}

// ---------------------------------------------------------------------------
// Stage 1: Y = X @ [Wu | Wl].  grid (128, 4). Epilogue writes swizzled Y.
// ---------------------------------------------------------------------------
__global__ __launch_bounds__(256, 2) void stage1_xw() {
    extern __shared__ char smem[];
    __shared__ __align__(8) uint64_t mb_full[3], mb_empty[3];
    const int tid = threadIdx.x, lane = tid & 31, wid = tid >> 5;
    const int warp_m = wid >> 2, warp_n = wid & 3;
    const int mb_ = blockIdx.x;               // 0..127
    const int ny = blockIdx.y;                // 0..3
    const int w = ny >> 1, nb = ny & 1;

    if (tid == 0) {
        #pragma unroll
        for (int i = 0; i < 3; i++) {
            MBAR_INIT(smem_u32(&mb_full[i]), 1);
            MBAR_INIT(smem_u32(&mb_empty[i]), 8);
        }
    }
    __syncthreads();

    const char* ah = (const char*)g_Xhi + (size_t)mb_ * BLOCK_BYTES;
    const char* al = (const char*)g_Xlo + (size_t)mb_ * BLOCK_BYTES;
    const char* bh = (const char*)g_Wthi + (size_t)(w * 2 + nb) * BLOCK_BYTES;
    const char* bl = (const char*)g_Wtlo + (size_t)(w * 2 + nb) * BLOCK_BYTES;

    float acc[4][4][4] = {};
    gemm_tile(acc, smem, mb_full, mb_empty, ah, al, bh, bl, warp_m, warp_n, lane, tid);

    // Epilogue: split fp32 -> bf16 hi/lo, write into swizzled tiled Y layout.
    const int g = lane >> 2, c2 = (lane & 3) * 2;
    #pragma unroll
    for (int mt = 0; mt < 4; mt++) {
        #pragma unroll
        for (int nt = 0; nt < 4; nt++) {
            const int nl = nb * 128 + warp_n * 32 + nt * 8 + c2;   // 0..255 within w
            const int kc = nl >> 5, q = (nl >> 3) & 3, e = nl & 7;
            #pragma unroll
            for (int h = 0; h < 2; h++) {
                const int r = warp_m * 64 + mt * 16 + g + 8 * h;   // row in block
                float x = acc[mt][nt][2 * h];
                float y = acc[mt][nt][2 * h + 1];
                __nv_bfloat16 xh = __float2bfloat16(x), yh = __float2bfloat16(y);
                __nv_bfloat16 xl = __float2bfloat16(x - __bfloat162float(xh));
                __nv_bfloat16 yl = __float2bfloat16(y - __bfloat162float(yh));
                size_t off = ((size_t)(w * 128 + mb_) * 8 + kc) * TILE_BYTES
                           + swz(r, q) + e * 2;
                *(uint32_t*)((char*)g_Yhi + off) = bfu(xh) | (bfu(yh) << 16);
                *(uint32_t*)((char*)g_Ylo + off) = bfu(xl) | (bfu(yl) << 16);
            }
        }
    }
}

// ---------------------------------------------------------------------------
// Stage 2: adj[b,p,q] = dot(Ysel[b,p,:], X[b,q,:]) + bias_sel.
// grid (72, 16): 36 upper + 36 lower tile-passes; diagonal tiles split.
// ---------------------------------------------------------------------------
__global__ __launch_bounds__(256, 2) void stage2_adj(const float* __restrict__ bu,
                                                     const float* __restrict__ bl,
                                                     float* __restrict__ out) {
    extern __shared__ char smem[];
    __shared__ __align__(8) uint64_t mb_full[3], mb_empty[3];
    const int tid = threadIdx.x, lane = tid & 31, wid = tid >> 5;
    const int warp_m = wid >> 2, warp_n = wid & 3;
    const int b = blockIdx.y;

    int t = blockIdx.x;                 // 0..71
    const int pass = (t >= 36) ? 1 : 0;
    int i = pass ? t - 36 : t;
    int r0 = 0;
    while (i >= 8 - r0) { i -= 8 - r0; r0++; }
    const int lo = r0, hi = r0 + i;     // lo <= hi
    const int pt = pass ? hi : lo;
    const int qt = pass ? lo : hi;
    const int p0 = pt * 128, q0 = qt * 128;

    if (tid == 0) {
        #pragma unroll
        for (int k = 0; k < 3; k++) {
            MBAR_INIT(smem_u32(&mb_full[k]), 1);
            MBAR_INIT(smem_u32(&mb_empty[k]), 8);
        }
    }
    __syncthreads();

    const float bias = pass ? __ldg(bl) : __ldg(bu);
    const char* yh = (const char*)g_Yhi + (size_t)(pass * 128 + b * 8 + pt) * BLOCK_BYTES;
    const char* yl = (const char*)g_Ylo + (size_t)(pass * 128 + b * 8 + pt) * BLOCK_BYTES;
    const char* xh = (const char*)g_Xhi + (size_t)(b * 8 + qt) * BLOCK_BYTES;
    const char* xl = (const char*)g_Xlo + (size_t)(b * 8 + qt) * BLOCK_BYTES;

    float acc[4][4][4] = {};
    gemm_tile(acc, smem, mb_full, mb_empty, yh, yl, xh, xl, warp_m, warp_n, lane, tid);

    const int g = lane >> 2, c2 = (lane & 3) * 2;
    #pragma unroll
    for (int mt = 0; mt < 4; mt++) {
        #pragma unroll
        for (int nt = 0; nt < 4; nt++) {
            const int q = q0 + warp_n * 32 + nt * 8 + c2;
            #pragma unroll
            for (int h = 0; h < 2; h++) {
                const int p = p0 + warp_m * 64 + mt * 16 + g + 8 * h;
                float* dst = out + ((size_t)b << 20) + ((size_t)p << 10) + q;
                float v0 = acc[mt][nt][2 * h] + bias;
                float v1 = acc[mt][nt][2 * h + 1] + bias;
                if (pt != qt) {
                    *(float2*)dst = make_float2(v0, v1);
                } else if (pass == 0) {
                    if (p <= q)     dst[0] = v0;
                    if (p <= q + 1) dst[1] = v1;
                } else {
                    if (p > q)      dst[0] = v0;
                    if (p > q + 1)  dst[1] = v1;
                }
            }
        }
    }
}

// ---------------------------------------------------------------------------
// kernel_launch
// ---------------------------------------------------------------------------
extern "C" void kernel_launch(void* const* d_in, const int* in_sizes, int n_in,
                              void* d_out, int out_size) {
    const float* feats = (const float*)d_in[0];
    const float* Wu    = (const float*)d_in[1];
    const float* bu    = (const float*)d_in[2];
    const float* Wl    = (const float*)d_in[3];
    const float* bl    = (const float*)d_in[4];
    float* out = (float*)d_out;

    cudaFuncSetAttribute(stage1_xw,  cudaFuncAttributeMaxDynamicSharedMemorySize, SMEM_TOTAL);
    cudaFuncSetAttribute(stage2_adj, cudaFuncAttributeMaxDynamicSharedMemorySize, SMEM_TOTAL);

    prep_split<<<2112, 256>>>(feats, Wu, Wl);
    stage1_xw<<<dim3(128, 4), 256, SMEM_TOTAL>>>();
    stage2_adj<<<dim3(72, 16), 256, SMEM_TOTAL>>>(bu, bl, out);
}